// round 6
// baseline (speedup 1.0000x reference)
#include <cuda_runtime.h>
#include <cuda_fp16.h>
#include <cstddef>
#include <cstdint>

// Problem constants (from reference):
//   pix_to_face : [N,H,W,K]      int32,  K = 4
//   bary_coords : [N,H,W,K,3]    float32
//   faces       : [F,3]          int32,  F = 200000
//   verts_colors: [V,3]          float32, V = 100000
//   output      : [N,H,W,3]      float32  (sample K=0 only)

#define KSAMP 4
#define PPT 4                    // pixels per thread (main kernel) — R4 sweet spot
#define F_MAX 200000
#define V_MAX 100000

__device__ __forceinline__ uint32_t h2_as_u32(__half2 h) {
    return *reinterpret_cast<uint32_t*>(&h);
}
__device__ __forceinline__ __half2 u32_as_h2(uint32_t u) {
    return *reinterpret_cast<__half2*>(&u);
}

// Per-vertex packed fp16 color: {(x,y),(z,pad)} = 8B. 100000*8 = 800KB, L2-resident.
__device__ uint2 g_verts_h[V_MAX];

// 32B per-face record: vertex slot j at 8B offset j: u[2j]=(cj.x,cj.y), u[2j+1]=(cj.z,pad).
struct alignas(32) FaceRec { uint32_t u[8]; };
__device__ FaceRec g_face_tab[F_MAX];

// 256-bit L2-cached gather (sm_103a LDG.E.256).
__device__ __forceinline__ void ldg256_cg(const void* p, uint32_t* a) {
    asm volatile("ld.global.cg.v8.b32 {%0,%1,%2,%3,%4,%5,%6,%7}, [%8];"
                 : "=r"(a[0]), "=r"(a[1]), "=r"(a[2]), "=r"(a[3]),
                   "=r"(a[4]), "=r"(a[5]), "=r"(a[6]), "=r"(a[7]) : "l"(p));
}

// ---------------------------------------------------------------------------
// Prepro 1: stream verts_colors [V,3] -> packed fp16 uint2 table (coalesced).
// ---------------------------------------------------------------------------
__global__ void __launch_bounds__(256)
pack_verts(const float* __restrict__ verts, int nverts)
{
    const int i = blockIdx.x * blockDim.x + threadIdx.x;
    if (i >= nverts) return;
    const float cx = __ldg(verts + (size_t)i * 3 + 0);
    const float cy = __ldg(verts + (size_t)i * 3 + 1);
    const float cz = __ldg(verts + (size_t)i * 3 + 2);
    uint2 h;
    h.x = h2_as_u32(__floats2half2_rn(cx, cy));
    h.y = h2_as_u32(__floats2half2_rn(cz, 0.0f));
    g_verts_h[i] = h;
}

// ---------------------------------------------------------------------------
// Prepro 2: one thread per FACE-VERTEX (F*3 threads): exactly ONE 8B gather.
// ---------------------------------------------------------------------------
__global__ void __launch_bounds__(256)
build_face_tab(const int* __restrict__ faces, int nfv)
{
    const int i = blockIdx.x * blockDim.x + threadIdx.x;
    if (i >= nfv) return;
    const int v = __ldg(faces + i);                 // coalesced
    const uint2 h = __ldg(g_verts_h + v);           // single 8B random gather
    const int face = i / 3;
    const int slot = i - face * 3;
    reinterpret_cast<uint2*>(&g_face_tab[face])[slot] = h;
}

// ---------------------------------------------------------------------------
// Main shader: 4 pixels/thread, one 256-bit gather per pixel. (R4 structure)
// ---------------------------------------------------------------------------
__global__ void __launch_bounds__(256)
unlit_shader_kernel(const int*   __restrict__ pix_to_face,
                    const float* __restrict__ bary,
                    float*       __restrict__ out,
                    int npix)
{
    const int t  = blockIdx.x * blockDim.x + threadIdx.x;
    const int p0 = t * PPT;
    if (p0 >= npix) return;
    const bool full = (p0 + PPT <= npix);

    // 1) Face indices (vectorized int4, coalesced; sample K=0 in .x).
    int f[PPT];
#pragma unroll
    for (int j = 0; j < PPT; ++j) {
        const int p = p0 + j;
        if (full || p < npix) {
            const int4 s = __ldcs(reinterpret_cast<const int4*>(pix_to_face) + p);
            f[j] = s.x;
        } else {
            f[j] = -1;
        }
    }

    // 2) Barycentric weights: unconditional float4 loads (addr independent of f),
    //    zeroed by select when background.
    float4 w[PPT];
#pragma unroll
    for (int j = 0; j < PPT; ++j) {
        const int p = p0 + j;
        float4 wv = (full || p < npix)
                  ? __ldcs(reinterpret_cast<const float4*>(bary + (size_t)p * (KSAMP * 3)))
                  : make_float4(0.f, 0.f, 0.f, 0.f);
        if (f[j] < 0) wv = make_float4(0.f, 0.f, 0.f, 0.f);
        w[j] = wv;
    }

    // 3) One 256-bit L2 gather per pixel from the fp16 face table.
    uint32_t g[PPT][8];
#pragma unroll
    for (int j = 0; j < PPT; ++j) {
        const int fi = (f[j] >= 0) ? f[j] : 0;
        ldg256_cg(&g_face_tab[fi], g[j]);
    }

    // 4) Unpack fp16 -> fp32, barycentric weighted sum.
    //    slot layout: g[2k]=(ck.x,ck.y), g[2k+1]=(ck.z,pad)
    float o[PPT * 3];
#pragma unroll
    for (int j = 0; j < PPT; ++j) {
        const float2 a0 = __half22float2(u32_as_h2(g[j][0])); // c0.x c0.y
        const float2 a1 = __half22float2(u32_as_h2(g[j][1])); // c0.z -
        const float2 b0 = __half22float2(u32_as_h2(g[j][2])); // c1.x c1.y
        const float2 b1 = __half22float2(u32_as_h2(g[j][3])); // c1.z -
        const float2 c0 = __half22float2(u32_as_h2(g[j][4])); // c2.x c2.y
        const float2 c1 = __half22float2(u32_as_h2(g[j][5])); // c2.z -
        const float wx = w[j].x, wy = w[j].y, wz = w[j].z;
        o[j * 3 + 0] = wx * a0.x + wy * b0.x + wz * c0.x;
        o[j * 3 + 1] = wx * a0.y + wy * b0.y + wz * c0.y;
        o[j * 3 + 2] = wx * a1.x + wy * b1.x + wz * c1.x;
    }

    // 5) Store 12 contiguous floats -> 3x STG.128, streaming.
    float* ob = out + (size_t)p0 * 3;
    if (full) {
        float4* o4 = reinterpret_cast<float4*>(ob);
        __stcs(o4 + 0, make_float4(o[0], o[1],  o[2],  o[3]));
        __stcs(o4 + 1, make_float4(o[4], o[5],  o[6],  o[7]));
        __stcs(o4 + 2, make_float4(o[8], o[9],  o[10], o[11]));
    } else {
#pragma unroll
        for (int j = 0; j < PPT; ++j) {
            const int p = p0 + j;
            if (p < npix) {
                ob[j * 3 + 0] = o[j * 3 + 0];
                ob[j * 3 + 1] = o[j * 3 + 1];
                ob[j * 3 + 2] = o[j * 3 + 2];
            }
        }
    }
}

extern "C" void kernel_launch(void* const* d_in, const int* in_sizes, int n_in,
                              void* d_out, int out_size)
{
    const int*   pix_to_face = (const int*)  d_in[0];
    const float* bary        = (const float*)d_in[1];
    const int*   faces       = (const int*)  d_in[2];
    const float* verts       = (const float*)d_in[3];
    float*       out         = (float*)      d_out;

    int nverts = in_sizes[3] / 3;
    if (nverts > V_MAX) nverts = V_MAX;
    int nfv = in_sizes[2];                       // F*3 face-vertices
    if (nfv > F_MAX * 3) nfv = F_MAX * 3;

    pack_verts<<<(nverts + 255) / 256, 256>>>(verts, nverts);
    build_face_tab<<<(nfv + 255) / 256, 256>>>(faces, nfv);

    const int npix     = in_sizes[0] / KSAMP;    // N*H*W
    const int nthreads = (npix + PPT - 1) / PPT;
    const int block    = 256;
    const int grid     = (nthreads + block - 1) / block;
    unlit_shader_kernel<<<grid, block>>>(pix_to_face, bary, out, npix);
}

// round 7
// speedup vs baseline: 1.0151x; 1.0151x over previous
#include <cuda_runtime.h>
#include <cuda_fp16.h>
#include <cstddef>
#include <cstdint>

// Problem constants (from reference):
//   pix_to_face : [N,H,W,K]      int32,  K = 4
//   bary_coords : [N,H,W,K,3]    float32
//   faces       : [F,3]          int32,  F = 200000
//   verts_colors: [V,3]          float32, V = 100000
//   output      : [N,H,W,3]      float32  (sample K=0 only)

#define KSAMP 4
#define PPT 4
#define F_MAX 200000
#define V_MAX 100000
#define BLOCK 256

__device__ __forceinline__ uint32_t h2_as_u32(__half2 h) {
    return *reinterpret_cast<uint32_t*>(&h);
}
__device__ __forceinline__ __half2 u32_as_h2(uint32_t u) {
    return *reinterpret_cast<__half2*>(&u);
}

// Per-vertex packed fp16 color: {(x,y),(z,pad)} = 8B. 800KB, L2-resident.
__device__ uint2 g_verts_h[V_MAX];
// 32B per-face record: slot j (8B): u[2j]=(cj.x,cj.y), u[2j+1]=(cj.z,pad). 6.4MB.
struct alignas(32) FaceRec { uint32_t u[8]; };
__device__ FaceRec g_face_tab[F_MAX];

// --------------------- software grid barrier (sense-reversing) --------------
// After an even number of barriers per launch both globals return to their
// initial state -> identical behavior on every graph replay.
__device__ unsigned g_bar_count = 0;
__device__ volatile unsigned g_bar_sense = 0;

__device__ __forceinline__ void grid_barrier(unsigned nblocks)
{
    __syncthreads();
    if (threadIdx.x == 0) {
        const unsigned s = g_bar_sense;
        __threadfence();                               // publish phase writes
        if (atomicAdd(&g_bar_count, 1u) == nblocks - 1u) {
            g_bar_count = 0;
            __threadfence();
            g_bar_sense = s ^ 1u;                      // release
        } else {
            while (g_bar_sense == s) { __nanosleep(40); }
            __threadfence();                           // acquire
        }
    }
    __syncthreads();
}

// 256-bit global load (sm_103a LDG.E.256); addr must be 32B-aligned.
__device__ __forceinline__ void ldg256(const void* p, uint32_t* a) {
    asm volatile("ld.global.v8.b32 {%0,%1,%2,%3,%4,%5,%6,%7}, [%8];"
                 : "=r"(a[0]), "=r"(a[1]), "=r"(a[2]), "=r"(a[3]),
                   "=r"(a[4]), "=r"(a[5]), "=r"(a[6]), "=r"(a[7]) : "l"(p));
}

// ---------------------------------------------------------------------------
// Single persistent fused kernel: pack verts | barrier | build face tab |
// barrier | shade pixels (grid-stride, PPT pixels per iteration).
// ---------------------------------------------------------------------------
__global__ void __launch_bounds__(BLOCK)
unlit_fused_kernel(const int*   __restrict__ pix_to_face,
                   const float* __restrict__ bary,
                   const int*   __restrict__ faces,
                   const float* __restrict__ verts,
                   float*       __restrict__ out,
                   int nverts, int nfv, int npix)
{
    const unsigned nblocks = gridDim.x;
    const int T   = (int)(gridDim.x * blockDim.x);
    const int tid = (int)(blockIdx.x * blockDim.x + threadIdx.x);

    // ---- Phase 0: pack vertex colors to fp16 (coalesced stream) ----
    for (int i = tid; i < nverts; i += T) {
        const float cx = __ldg(verts + (size_t)i * 3 + 0);
        const float cy = __ldg(verts + (size_t)i * 3 + 1);
        const float cz = __ldg(verts + (size_t)i * 3 + 2);
        uint2 h;
        h.x = h2_as_u32(__floats2half2_rn(cx, cy));
        h.y = h2_as_u32(__floats2half2_rn(cz, 0.0f));
        g_verts_h[i] = h;
    }

    grid_barrier(nblocks);

    // ---- Phase 1: one 8B gather per face-vertex ----
    for (int i = tid; i < nfv; i += T) {
        const int v = __ldg(faces + i);                // coalesced
        const uint2 h = *(g_verts_h + v);              // 8B random gather (L2)
        const int face = i / 3;
        const int slot = i - face * 3;
        reinterpret_cast<uint2*>(&g_face_tab[face])[slot] = h;
    }

    grid_barrier(nblocks);

    // ---- Phase 2: shade pixels, PPT per iteration, grid-stride ----
    const int ngroups = (npix + PPT - 1) / PPT;
    for (int gidx = tid; gidx < ngroups; gidx += T) {
        const int p0 = gidx * PPT;
        const bool full = (p0 + PPT <= npix);

        // 1) Face indices (int4 vector load; sample K=0 in .x).
        int f[PPT];
#pragma unroll
        for (int j = 0; j < PPT; ++j) {
            const int p = p0 + j;
            if (full || p < npix) {
                const int4 s = __ldcs(reinterpret_cast<const int4*>(pix_to_face) + p);
                f[j] = s.x;
            } else {
                f[j] = -1;
            }
        }

        // 2) Barycentric weights (float4 @ 48B stride).
        float4 w[PPT];
#pragma unroll
        for (int j = 0; j < PPT; ++j) {
            const int p = p0 + j;
            w[j] = (f[j] >= 0)
                 ? __ldcs(reinterpret_cast<const float4*>(bary + (size_t)p * (KSAMP * 3)))
                 : make_float4(0.f, 0.f, 0.f, 0.f);
        }

        // 3) One 256-bit gather per pixel from the L2-resident fp16 table.
        uint32_t g[PPT][8];
#pragma unroll
        for (int j = 0; j < PPT; ++j) {
            const int fi = (f[j] >= 0) ? f[j] : 0;
            ldg256(&g_face_tab[fi], g[j]);
        }

        // 4) Unpack + weighted sum. slot k: g[2k]=(ck.x,ck.y), g[2k+1]=(ck.z,-)
        float o[PPT * 3];
#pragma unroll
        for (int j = 0; j < PPT; ++j) {
            const float2 a0 = __half22float2(u32_as_h2(g[j][0]));
            const float2 a1 = __half22float2(u32_as_h2(g[j][1]));
            const float2 b0 = __half22float2(u32_as_h2(g[j][2]));
            const float2 b1 = __half22float2(u32_as_h2(g[j][3]));
            const float2 c0 = __half22float2(u32_as_h2(g[j][4]));
            const float2 c1 = __half22float2(u32_as_h2(g[j][5]));
            const float wx = w[j].x, wy = w[j].y, wz = w[j].z;
            o[j * 3 + 0] = wx * a0.x + wy * b0.x + wz * c0.x;
            o[j * 3 + 1] = wx * a0.y + wy * b0.y + wz * c0.y;
            o[j * 3 + 2] = wx * a1.x + wy * b1.x + wz * c1.x;
        }

        // 5) 12 contiguous floats -> 3x STG.128, streaming.
        float* ob = out + (size_t)p0 * 3;
        if (full) {
            float4* o4 = reinterpret_cast<float4*>(ob);
            __stcs(o4 + 0, make_float4(o[0], o[1],  o[2],  o[3]));
            __stcs(o4 + 1, make_float4(o[4], o[5],  o[6],  o[7]));
            __stcs(o4 + 2, make_float4(o[8], o[9],  o[10], o[11]));
        } else {
#pragma unroll
            for (int j = 0; j < PPT; ++j) {
                const int p = p0 + j;
                if (p < npix) {
                    ob[j * 3 + 0] = o[j * 3 + 0];
                    ob[j * 3 + 1] = o[j * 3 + 1];
                    ob[j * 3 + 2] = o[j * 3 + 2];
                }
            }
        }
    }
}

extern "C" void kernel_launch(void* const* d_in, const int* in_sizes, int n_in,
                              void* d_out, int out_size)
{
    const int*   pix_to_face = (const int*)  d_in[0];
    const float* bary        = (const float*)d_in[1];
    const int*   faces       = (const int*)  d_in[2];
    const float* verts       = (const float*)d_in[3];
    float*       out         = (float*)      d_out;

    int nverts = in_sizes[3] / 3;
    if (nverts > V_MAX) nverts = V_MAX;
    int nfv = in_sizes[2];
    if (nfv > F_MAX * 3) nfv = F_MAX * 3;
    const int npix = in_sizes[0] / KSAMP;

    // Persistent grid sized to guaranteed co-residency (barrier safety).
    int dev = 0;
    cudaGetDevice(&dev);
    int sms = 148;
    cudaDeviceGetAttribute(&sms, cudaDevAttrMultiProcessorCount, dev);
    int occ = 1;
    cudaOccupancyMaxActiveBlocksPerMultiprocessor(&occ, unlit_fused_kernel, BLOCK, 0);
    if (occ < 1) occ = 1;
    int grid = sms * occ;
    // Never launch more blocks than there are PPT-groups of work, but keep
    // at least 1 block. (npix/PPT ~ 524288 >> grid here.)
    const int ngroups = (npix + PPT - 1) / PPT;
    if (grid > ngroups) grid = ngroups;
    if (grid < 1) grid = 1;

    unlit_fused_kernel<<<grid, BLOCK>>>(pix_to_face, bary, faces, verts, out,
                                        nverts, nfv, npix);
}

// round 8
// speedup vs baseline: 1.1437x; 1.1266x over previous
#include <cuda_runtime.h>
#include <cuda_fp16.h>
#include <cstddef>
#include <cstdint>

// Problem constants (from reference):
//   pix_to_face : [N,H,W,K]      int32,  K = 4
//   bary_coords : [N,H,W,K,3]    float32
//   faces       : [F,3]          int32,  F = 200000
//   verts_colors: [V,3]          float32, V = 100000
//   output      : [N,H,W,3]      float32  (sample K=0 only)

#define KSAMP 4
#define PPT 4
#define F_MAX 200000
#define BLOCK 256

__device__ __forceinline__ uint32_t h2_as_u32(__half2 h) {
    return *reinterpret_cast<uint32_t*>(&h);
}
__device__ __forceinline__ __half2 u32_as_h2(uint32_t u) {
    return *reinterpret_cast<__half2*>(&u);
}

// 32B per-face record: slot k (8B): u[2k]=(ck.x,ck.y), u[2k+1]=(ck.z,pad). 6.4MB, L2-resident.
struct alignas(32) FaceRec { uint32_t u[8]; };
__device__ FaceRec g_face_tab[F_MAX];

// 256-bit global load (sm_103a LDG.E.256); addr must be 32B-aligned.
__device__ __forceinline__ void ldg256(const void* p, uint32_t* a) {
    asm volatile("ld.global.v8.b32 {%0,%1,%2,%3,%4,%5,%6,%7}, [%8];"
                 : "=r"(a[0]), "=r"(a[1]), "=r"(a[2]), "=r"(a[3]),
                   "=r"(a[4]), "=r"(a[5]), "=r"(a[6]), "=r"(a[7]) : "l"(p));
}

// ---------------------------------------------------------------------------
// Prepro: one thread per FACE-VERTEX (F*3). 1 coalesced idx load, 3 scalar
// vertex-color gathers, fp16 pack, one 8B store. Triggers PDL early so the
// main grid can start its streaming prologue while this drains.
// ---------------------------------------------------------------------------
__global__ void __launch_bounds__(BLOCK)
build_face_tab(const int*   __restrict__ faces,
               const float* __restrict__ verts,
               int nfv)
{
    const int i = blockIdx.x * blockDim.x + threadIdx.x;
    if (i < nfv) {
        const int v = __ldg(faces + i);
        const float cx = __ldg(verts + (size_t)v * 3 + 0);
        const float cy = __ldg(verts + (size_t)v * 3 + 1);
        const float cz = __ldg(verts + (size_t)v * 3 + 2);
        uint2 h;
        h.x = h2_as_u32(__floats2half2_rn(cx, cy));
        h.y = h2_as_u32(__floats2half2_rn(cz, 0.0f));
        const int face = i / 3;
        const int slot = i - face * 3;
        reinterpret_cast<uint2*>(&g_face_tab[face])[slot] = h;
    }
    // Allow the dependent (main) grid to begin launching now; its
    // cudaGridDependencySynchronize() still waits for our completion+flush.
    cudaTriggerProgrammaticLaunchCompletion();
}

// ---------------------------------------------------------------------------
// Main shader (R4 structure): 4 pixels/thread, one 256-bit gather per pixel.
// PDL: streaming prologue first, then grid-dependency sync, then gathers.
// ---------------------------------------------------------------------------
__global__ void __launch_bounds__(BLOCK)
unlit_shader_kernel(const int*   __restrict__ pix_to_face,
                    const float* __restrict__ bary,
                    float*       __restrict__ out,
                    int npix)
{
    const int t  = blockIdx.x * blockDim.x + threadIdx.x;
    const int p0 = t * PPT;
    if (p0 >= npix) {
        cudaGridDependencySynchronize();
        return;
    }
    const bool full = (p0 + PPT <= npix);

    // 1) Face indices (vectorized int4, coalesced; sample K=0 in .x).
    //    No dependency on the prepro table -> runs before the grid sync.
    int f[PPT];
#pragma unroll
    for (int j = 0; j < PPT; ++j) {
        const int p = p0 + j;
        if (full || p < npix) {
            const int4 s = __ldcs(reinterpret_cast<const int4*>(pix_to_face) + p);
            f[j] = s.x;
        } else {
            f[j] = -1;
        }
    }

    // 2) Barycentric weights (float4 @ 48B stride, streaming).
    float4 w[PPT];
#pragma unroll
    for (int j = 0; j < PPT; ++j) {
        const int p = p0 + j;
        w[j] = (f[j] >= 0)
             ? __ldcs(reinterpret_cast<const float4*>(bary + (size_t)p * (KSAMP * 3)))
             : make_float4(0.f, 0.f, 0.f, 0.f);
    }

    // ---- PDL: wait until prepro's table writes are complete & visible ----
    cudaGridDependencySynchronize();

    // 3) One 256-bit gather per pixel from the L2-resident fp16 table.
    uint32_t g[PPT][8];
#pragma unroll
    for (int j = 0; j < PPT; ++j) {
        const int fi = (f[j] >= 0) ? f[j] : 0;
        ldg256(&g_face_tab[fi], g[j]);
    }

    // 4) Unpack fp16 -> fp32, barycentric weighted sum.
    //    slot k: g[2k]=(ck.x,ck.y), g[2k+1]=(ck.z,pad)
    float o[PPT * 3];
#pragma unroll
    for (int j = 0; j < PPT; ++j) {
        const float2 a0 = __half22float2(u32_as_h2(g[j][0]));
        const float2 a1 = __half22float2(u32_as_h2(g[j][1]));
        const float2 b0 = __half22float2(u32_as_h2(g[j][2]));
        const float2 b1 = __half22float2(u32_as_h2(g[j][3]));
        const float2 c0 = __half22float2(u32_as_h2(g[j][4]));
        const float2 c1 = __half22float2(u32_as_h2(g[j][5]));
        const float wx = w[j].x, wy = w[j].y, wz = w[j].z;
        o[j * 3 + 0] = wx * a0.x + wy * b0.x + wz * c0.x;
        o[j * 3 + 1] = wx * a0.y + wy * b0.y + wz * c0.y;
        o[j * 3 + 2] = wx * a1.x + wy * b1.x + wz * c1.x;
    }

    // 5) Store 12 contiguous floats -> 3x STG.128, streaming.
    float* ob = out + (size_t)p0 * 3;
    if (full) {
        float4* o4 = reinterpret_cast<float4*>(ob);
        __stcs(o4 + 0, make_float4(o[0], o[1],  o[2],  o[3]));
        __stcs(o4 + 1, make_float4(o[4], o[5],  o[6],  o[7]));
        __stcs(o4 + 2, make_float4(o[8], o[9],  o[10], o[11]));
    } else {
#pragma unroll
        for (int j = 0; j < PPT; ++j) {
            const int p = p0 + j;
            if (p < npix) {
                ob[j * 3 + 0] = o[j * 3 + 0];
                ob[j * 3 + 1] = o[j * 3 + 1];
                ob[j * 3 + 2] = o[j * 3 + 2];
            }
        }
    }
}

extern "C" void kernel_launch(void* const* d_in, const int* in_sizes, int n_in,
                              void* d_out, int out_size)
{
    const int*   pix_to_face = (const int*)  d_in[0];
    const float* bary        = (const float*)d_in[1];
    const int*   faces       = (const int*)  d_in[2];
    const float* verts       = (const float*)d_in[3];
    float*       out         = (float*)      d_out;

    int nfv = in_sizes[2];                       // F*3 face-vertices
    if (nfv > F_MAX * 3) nfv = F_MAX * 3;
    const int npix = in_sizes[0] / KSAMP;        // N*H*W

    // Prepro (primary).
    build_face_tab<<<(nfv + BLOCK - 1) / BLOCK, BLOCK>>>(faces, verts, nfv);

    // Main (secondary) with programmatic dependent launch.
    const int nthreads = (npix + PPT - 1) / PPT;
    const int grid     = (nthreads + BLOCK - 1) / BLOCK;

    cudaLaunchConfig_t cfg = {};
    cfg.gridDim         = dim3((unsigned)grid, 1, 1);
    cfg.blockDim        = dim3(BLOCK, 1, 1);
    cfg.dynamicSmemBytes = 0;
    cfg.stream          = 0;   // same (legacy) stream the harness captures

    cudaLaunchAttribute attr[1];
    attr[0].id = cudaLaunchAttributeProgrammaticStreamSerialization;
    attr[0].val.programmaticStreamSerializationAllowed = 1;
    cfg.attrs    = attr;
    cfg.numAttrs = 1;

    cudaLaunchKernelEx(&cfg, unlit_shader_kernel, pix_to_face, bary, out, npix);
}